// round 1
// baseline (speedup 1.0000x reference)
#include <cuda_runtime.h>
#include <cuda_bf16.h>

#define W 512
#define H 512
#define IMGS 128                      // 16 * 8
#define STRIP 16                      // output rows per warp
#define STRIPS_PER_IMG (H / STRIP)    // 32
#define WARPS_TOTAL (IMGS * STRIPS_PER_IMG)   // 4096
#define BLOCK 256
#define WARPS_PER_BLOCK (BLOCK / 32)  // 8
#define GRID (WARPS_TOTAL / WARPS_PER_BLOCK)  // 512
#define NELEM 33554432.0f             // 16*8*512*512

__device__ float g_partials[GRID];

// Load one full 16-float segment of a row (4x LDG.128, coalesced across warp)
__device__ __forceinline__ void load_row(const float* __restrict__ row, int lane, float x[16]) {
    const float4* p = reinterpret_cast<const float4*>(row) + lane * 4;
#pragma unroll
    for (int k = 0; k < 4; k++) {
        float4 v = p[k];
        x[4*k+0] = v.x; x[4*k+1] = v.y; x[4*k+2] = v.z; x[4*k+3] = v.w;
    }
}

// Horizontal erosion: er[c] = min(vm[c-1], vm[c]), vm[-1] := vm[0] at image edge.
// Warp spans the full 512-wide row, so only one shuffle needed.
__device__ __forceinline__ void hmin_row(const float vm[16], int lane, float er[16]) {
    float left = __shfl_up_sync(0xffffffffu, vm[15], 1);
    if (lane == 0) left = vm[0];           // symmetric pad: x[-1] = x[0]
    er[0] = fminf(left, vm[0]);
#pragma unroll
    for (int i = 1; i < 16; i++) er[i] = fminf(vm[i-1], vm[i]);
}

// Horizontal dilation + loss accumulation: di[c] = max(hv[c], hv[c+1]),
// hv[512] := hv[511] at image edge. acc += (xp - di)^2
__device__ __forceinline__ void hmax_emit(const float hv[16], int lane,
                                          const float xp[16], float& acc) {
    float right = __shfl_down_sync(0xffffffffu, hv[0], 1);
    if (lane == 31) right = hv[15];        // symmetric pad: er[512] = er[511]
#pragma unroll
    for (int i = 0; i < 15; i++) {
        float di = fmaxf(hv[i], hv[i+1]);
        float d = xp[i] - di;
        acc = fmaf(d, d, acc);
    }
    float di = fmaxf(hv[15], right);
    float d = xp[15] - di;
    acc = fmaf(d, d, acc);
}

__global__ void __launch_bounds__(BLOCK)
opening_loss_kernel(const float* __restrict__ labels) {
    const int lane  = threadIdx.x & 31;
    const int warp  = (blockIdx.x * BLOCK + threadIdx.x) >> 5;
    const int img   = warp / STRIPS_PER_IMG;
    const int strip = warp % STRIPS_PER_IMG;
    const float* base = labels + (size_t)img * (W * H);
    const int r0 = strip * STRIP;

    float xp[16], xc[16], vm[16], erp[16], ern[16], hv[16];
    float acc = 0.0f;

    // Prologue: establish erp = er[r0] (needs x[r0-1], x[r0]); xp = x[r0]
    load_row(base + (size_t)((r0 > 0) ? (r0 - 1) : 0) * W, lane, xp);
    load_row(base + (size_t)r0 * W, lane, xc);
#pragma unroll
    for (int i = 0; i < 16; i++) vm[i] = fminf(xp[i], xc[i]);   // vertical erosion, x[-1]=x[0]
    hmin_row(vm, lane, erp);
#pragma unroll
    for (int i = 0; i < 16; i++) xp[i] = xc[i];

    // Stream rows r0+1 .. r0+16 (clamped to 511), emitting output row r-1 each step.
    const int rend = (r0 + STRIP < H) ? (r0 + STRIP) : (H - 1);  // inclusive
    for (int r = r0 + 1; r <= rend; r++) {
        load_row(base + (size_t)r * W, lane, xc);
#pragma unroll
        for (int i = 0; i < 16; i++) vm[i] = fminf(xp[i], xc[i]);
        hmin_row(vm, lane, ern);                                 // er[r]
#pragma unroll
        for (int i = 0; i < 16; i++) hv[i] = fmaxf(erp[i], ern[i]);  // vertical dilation for row r-1
        hmax_emit(hv, lane, xp, acc);                            // loss of row r-1
#pragma unroll
        for (int i = 0; i < 16; i++) { xp[i] = xc[i]; erp[i] = ern[i]; }
    }
    // Bottom strip: emit row 511 (er[512] = er[511] -> hv = erp)
    if (r0 + STRIP == H) {
        hmax_emit(erp, lane, xp, acc);
    }

    // Deterministic reduction: warp shuffle -> shared -> per-block partial
#pragma unroll
    for (int off = 16; off; off >>= 1)
        acc += __shfl_xor_sync(0xffffffffu, acc, off);

    __shared__ float s[WARPS_PER_BLOCK];
    if (lane == 0) s[threadIdx.x >> 5] = acc;
    __syncthreads();
    if (threadIdx.x == 0) {
        float t = 0.0f;
#pragma unroll
        for (int i = 0; i < WARPS_PER_BLOCK; i++) t += s[i];
        g_partials[blockIdx.x] = t;
    }
}

__global__ void __launch_bounds__(GRID)
reduce_kernel(float* __restrict__ out) {
    __shared__ float s[GRID];
    const int t = threadIdx.x;
    s[t] = g_partials[t];
    __syncthreads();
#pragma unroll
    for (int off = GRID / 2; off > 0; off >>= 1) {
        if (t < off) s[t] += s[t + off];
        __syncthreads();
    }
    if (t == 0) out[0] = s[0] * (1.0f / NELEM);
}

extern "C" void kernel_launch(void* const* d_in, const int* in_sizes, int n_in,
                              void* d_out, int out_size) {
    const float* labels = (const float*)d_in[0];
    float* out = (float*)d_out;
    opening_loss_kernel<<<GRID, BLOCK>>>(labels);
    reduce_kernel<<<1, GRID>>>(out);
}

// round 2
// speedup vs baseline: 1.0504x; 1.0504x over previous
#include <cuda_runtime.h>
#include <cuda_bf16.h>

#define W 512
#define H 512
#define IMGS 128                      // 16 * 8
#define STRIP 16                      // output rows per warp
#define STRIPS_PER_IMG (H / STRIP)    // 32
#define WARPS_TOTAL (IMGS * STRIPS_PER_IMG)   // 4096
#define BLOCK 256
#define WARPS_PER_BLOCK (BLOCK / 32)  // 8
#define GRID (WARPS_TOTAL / WARPS_PER_BLOCK)  // 512
#define NELEM 33554432.0f             // 16*8*512*512

__device__ float g_partials[GRID];
__device__ unsigned int g_count;      // zero-initialized; last block resets it

// Load one full 16-float segment of a row (4x LDG.128, coalesced across warp)
__device__ __forceinline__ void load_row(const float* __restrict__ row, int lane, float x[16]) {
    const float4* p = reinterpret_cast<const float4*>(row) + lane * 4;
#pragma unroll
    for (int k = 0; k < 4; k++) {
        float4 v = p[k];
        x[4*k+0] = v.x; x[4*k+1] = v.y; x[4*k+2] = v.z; x[4*k+3] = v.w;
    }
}

// Horizontal erosion: er[c] = min(vm[c-1], vm[c]), vm[-1] := vm[0] at image edge.
__device__ __forceinline__ void hmin_row(const float vm[16], int lane, float er[16]) {
    float left = __shfl_up_sync(0xffffffffu, vm[15], 1);
    if (lane == 0) left = vm[0];           // symmetric pad: x[-1] = x[0]
    er[0] = fminf(left, vm[0]);
#pragma unroll
    for (int i = 1; i < 16; i++) er[i] = fminf(vm[i-1], vm[i]);
}

// Horizontal dilation + loss accumulation: di[c] = max(hv[c], hv[c+1]),
// hv[512] := hv[511] at image edge. acc += (xp - di)^2
__device__ __forceinline__ void hmax_emit(const float hv[16], int lane,
                                          const float xp[16], float& acc) {
    float right = __shfl_down_sync(0xffffffffu, hv[0], 1);
    if (lane == 31) right = hv[15];        // symmetric pad: er[512] = er[511]
#pragma unroll
    for (int i = 0; i < 15; i++) {
        float di = fmaxf(hv[i], hv[i+1]);
        float d = xp[i] - di;
        acc = fmaf(d, d, acc);
    }
    float di = fmaxf(hv[15], right);
    float d = xp[15] - di;
    acc = fmaf(d, d, acc);
}

// One streaming step: consume row r, emit loss for row r-1.
__device__ __forceinline__ void step(const float* __restrict__ base, int r, int lane,
                                     float xp[16], float erp[16], float& acc) {
    float xc[16], vm[16], ern[16], hv[16];
    load_row(base + (size_t)r * W, lane, xc);
#pragma unroll
    for (int i = 0; i < 16; i++) vm[i] = fminf(xp[i], xc[i]);   // vertical erosion
    hmin_row(vm, lane, ern);                                    // er[r]
#pragma unroll
    for (int i = 0; i < 16; i++) hv[i] = fmaxf(erp[i], ern[i]); // vertical dilation, row r-1
    hmax_emit(hv, lane, xp, acc);                               // loss of row r-1
#pragma unroll
    for (int i = 0; i < 16; i++) { xp[i] = xc[i]; erp[i] = ern[i]; }
}

__global__ void __launch_bounds__(BLOCK)
opening_loss_kernel(const float* __restrict__ labels, float* __restrict__ out) {
    const int lane  = threadIdx.x & 31;
    const int warp  = (blockIdx.x * BLOCK + threadIdx.x) >> 5;
    const int img   = warp / STRIPS_PER_IMG;
    const int strip = warp % STRIPS_PER_IMG;
    const float* base = labels + (size_t)img * (W * H);
    const int r0 = strip * STRIP;

    float xp[16], xc[16], vm[16], erp[16];
    float acc = 0.0f;

    // Prologue: erp = er[r0] (needs x[r0-1], x[r0]); xp = x[r0]
    load_row(base + (size_t)((r0 > 0) ? (r0 - 1) : 0) * W, lane, xp);
    load_row(base + (size_t)r0 * W, lane, xc);
#pragma unroll
    for (int i = 0; i < 16; i++) vm[i] = fminf(xp[i], xc[i]);   // x[-1] = x[0]
    hmin_row(vm, lane, erp);
#pragma unroll
    for (int i = 0; i < 16; i++) xp[i] = xc[i];

    if (r0 + STRIP < H) {
        // Fast path (31/32 strips): exactly STRIP iterations, unrolled so the
        // independent row loads of consecutive iterations get front-batched (MLP up).
#pragma unroll 4
        for (int k = 1; k <= STRIP; k++)
            step(base, r0 + k, lane, xp, erp, acc);
    } else {
        // Bottom strip: rows r0+1 .. 511, then emit row 511 with er[512]=er[511].
        for (int r = r0 + 1; r <= H - 1; r++)
            step(base, r, lane, xp, erp, acc);
        hmax_emit(erp, lane, xp, acc);
    }

    // Deterministic block reduction: warp shuffle -> shared -> per-block partial
#pragma unroll
    for (int off = 16; off; off >>= 1)
        acc += __shfl_xor_sync(0xffffffffu, acc, off);

    __shared__ float s[WARPS_PER_BLOCK];
    __shared__ bool is_last;
    if (lane == 0) s[threadIdx.x >> 5] = acc;
    __syncthreads();
    if (threadIdx.x == 0) {
        float t = 0.0f;
#pragma unroll
        for (int i = 0; i < WARPS_PER_BLOCK; i++) t += s[i];
        g_partials[blockIdx.x] = t;
        __threadfence();
        unsigned v = atomicAdd(&g_count, 1u);
        is_last = (v == GRID - 1);
    }
    __syncthreads();

    // Last block to finish performs the deterministic final tree reduction.
    if (is_last) {
        __shared__ float r[BLOCK];
        float v = g_partials[threadIdx.x] + g_partials[threadIdx.x + BLOCK];
        r[threadIdx.x] = v;
        __syncthreads();
#pragma unroll
        for (int off = BLOCK / 2; off > 0; off >>= 1) {
            if (threadIdx.x < off) r[threadIdx.x] += r[threadIdx.x + off];
            __syncthreads();
        }
        if (threadIdx.x == 0) {
            out[0] = r[0] * (1.0f / NELEM);
            g_count = 0;   // reset for next (graph-replayed) launch
        }
    }
}

extern "C" void kernel_launch(void* const* d_in, const int* in_sizes, int n_in,
                              void* d_out, int out_size) {
    const float* labels = (const float*)d_in[0];
    float* out = (float*)d_out;
    opening_loss_kernel<<<GRID, BLOCK>>>(labels, out);
}

// round 3
// speedup vs baseline: 1.1969x; 1.1395x over previous
#include <cuda_runtime.h>
#include <cuda_bf16.h>

#define W 512
#define H 512
#define IMGS 128                       // 16 * 8
#define STRIP 32                       // output rows per warp
#define STRIPS (H / STRIP)             // 16
#define SEGS 2                         // column segments per row
#define SEGW 256                       // cols per warp segment
#define CPT 8                          // cols per thread
#define WARPS_TOTAL (IMGS * STRIPS * SEGS)   // 4096
#define BLOCK 256
#define WPB (BLOCK / 32)               // 8
#define GRID (WARPS_TOTAL / WPB)       // 512  (== one full wave at 4 blocks/SM)
#define NELEM 33554432.0f
#define FULLM 0xffffffffu

__device__ float g_partials[GRID];
__device__ unsigned int g_count;       // zero-init; last block resets

struct Carry {
    float xp[CPT];    // x[r-1] at this thread's cols
    float erp[CPT];   // er[r-1]
    float xLp, xRp;   // halo cols of x[r-1] (lane0 / lane31 only)
    float erpR;       // er[r-1][c1+1]     (lane31 only)
};

__device__ __forceinline__ void load8(const float* __restrict__ p, float x[CPT]) {
    float4 a = *reinterpret_cast<const float4*>(p);
    float4 b = *reinterpret_cast<const float4*>(p + 4);
    x[0]=a.x; x[1]=a.y; x[2]=a.z; x[3]=a.w;
    x[4]=b.x; x[5]=b.y; x[6]=b.z; x[7]=b.w;
}

// Consume row r, emit loss for row r-1.
__device__ __forceinline__ void step_row(const float* __restrict__ tp,
                                         const float* __restrict__ row,
                                         int lane, int cL, int cR, bool rightEdge,
                                         Carry& C, float& acc) {
    float xc[CPT];
    load8(tp, xc);
    float xLc = (lane == 0)                ? row[cL] : 0.0f;
    float xRc = (!rightEdge && lane == 31) ? row[cR] : 0.0f;

    float vm[CPT];
#pragma unroll
    for (int i = 0; i < CPT; i++) vm[i] = fminf(C.xp[i], xc[i]);  // vertical erosion
    float vmL = fminf(C.xLp, xLc);
    float vmR = fminf(C.xRp, xRc);

    // horizontal erosion: er[c] = min(vm[c-1], vm[c])
    float left = __shfl_up_sync(FULLM, vm[CPT-1], 1);
    if (lane == 0) left = vmL;                       // x[-1]=x[0] pad handled via cL clamp
    float ern[CPT];
    ern[0] = fminf(left, vm[0]);
#pragma unroll
    for (int i = 1; i < CPT; i++) ern[i] = fminf(vm[i-1], vm[i]);
    float ernR = fminf(vm[CPT-1], vmR);              // er[r][c1+1] (lane31)

    // vertical dilation for row r-1: h = max(er[r-1], er[r])
    float h[CPT];
#pragma unroll
    for (int i = 0; i < CPT; i++) h[i] = fmaxf(C.erp[i], ern[i]);
    float hR = fmaxf(C.erpR, ernR);

    // horizontal dilation + loss: di[c] = max(h[c], h[c+1])
    float hn = __shfl_down_sync(FULLM, h[0], 1);
    if (lane == 31) hn = rightEdge ? h[CPT-1] : hR;  // er[512]=er[511] pad at image edge
#pragma unroll
    for (int i = 0; i < CPT-1; i++) {
        float di = fmaxf(h[i], h[i+1]);
        float d = C.xp[i] - di;
        acc = fmaf(d, d, acc);
    }
    {
        float di = fmaxf(h[CPT-1], hn);
        float d = C.xp[CPT-1] - di;
        acc = fmaf(d, d, acc);
    }

#pragma unroll
    for (int i = 0; i < CPT; i++) { C.xp[i] = xc[i]; C.erp[i] = ern[i]; }
    C.xLp = xLc; C.xRp = xRc; C.erpR = ernR;
}

// Emit bottom image row (r = H-1): er[H] := er[H-1], so h == erp.
__device__ __forceinline__ void final_emit(int lane, bool rightEdge, Carry& C, float& acc) {
    float hn = __shfl_down_sync(FULLM, C.erp[0], 1);
    if (lane == 31) hn = rightEdge ? C.erp[CPT-1] : C.erpR;
#pragma unroll
    for (int i = 0; i < CPT-1; i++) {
        float di = fmaxf(C.erp[i], C.erp[i+1]);
        float d = C.xp[i] - di;
        acc = fmaf(d, d, acc);
    }
    float di = fmaxf(C.erp[CPT-1], hn);
    float d = C.xp[CPT-1] - di;
    acc = fmaf(d, d, acc);
}

__global__ void __launch_bounds__(BLOCK, 4)
opening_loss_kernel(const float* __restrict__ labels, float* __restrict__ out) {
    const int lane = threadIdx.x & 31;
    const int warp = blockIdx.x * WPB + (threadIdx.x >> 5);
    const int seg   = warp & (SEGS - 1);
    const int t     = warp >> 1;
    const int strip = t & (STRIPS - 1);
    const int img   = t >> 4;                        // STRIPS==16

    const float* base = labels + (size_t)img * (W * H);
    const int r0 = strip * STRIP;
    const int c0 = seg * SEGW;
    const bool rightEdge = (seg == SEGS - 1);
    const int cL = (c0 == 0) ? 0 : c0 - 1;           // clamp == symmetric pad
    const int cR = rightEdge ? (W - 1) : c0 + SEGW;  // never loaded when rightEdge
    const int tcol = c0 + lane * CPT;

    Carry C;
    float acc = 0.0f;

    // Prologue: erp = er[r0], xp = x[r0]
    {
        const int rm1 = (r0 > 0) ? r0 - 1 : 0;       // x[-1]=x[0] pad
        const float* rowA = base + (size_t)rm1 * W;
        const float* rowB = base + (size_t)r0  * W;
        float xa[CPT], xb[CPT];
        load8(rowA + tcol, xa);
        load8(rowB + tcol, xb);
        float xLa = (lane == 0) ? rowA[cL] : 0.0f;
        float xLb = (lane == 0) ? rowB[cL] : 0.0f;
        float xRa = (!rightEdge && lane == 31) ? rowA[cR] : 0.0f;
        float xRb = (!rightEdge && lane == 31) ? rowB[cR] : 0.0f;

        float vm[CPT];
#pragma unroll
        for (int i = 0; i < CPT; i++) vm[i] = fminf(xa[i], xb[i]);
        float vmL = fminf(xLa, xLb);
        float vmR = fminf(xRa, xRb);

        float left = __shfl_up_sync(FULLM, vm[CPT-1], 1);
        if (lane == 0) left = vmL;
        C.erp[0] = fminf(left, vm[0]);
#pragma unroll
        for (int i = 1; i < CPT; i++) C.erp[i] = fminf(vm[i-1], vm[i]);
        C.erpR = fminf(vm[CPT-1], vmR);
#pragma unroll
        for (int i = 0; i < CPT; i++) C.xp[i] = xb[i];
        C.xLp = xLb; C.xRp = xRb;
    }

    if (r0 + STRIP < H) {
        const float* row = base + (size_t)(r0 + 1) * W;
#pragma unroll 4
        for (int k = 0; k < STRIP; k++) {
            step_row(row + tcol, row, lane, cL, cR, rightEdge, C, acc);
            row += W;
        }
    } else {
        const float* row = base + (size_t)(r0 + 1) * W;
        for (int r = r0 + 1; r < H; r++) {
            step_row(row + tcol, row, lane, cL, cR, rightEdge, C, acc);
            row += W;
        }
        final_emit(lane, rightEdge, C, acc);
    }

    // Deterministic block reduction
#pragma unroll
    for (int off = 16; off; off >>= 1)
        acc += __shfl_xor_sync(FULLM, acc, off);

    __shared__ float s[WPB];
    __shared__ bool is_last;
    if (lane == 0) s[threadIdx.x >> 5] = acc;
    __syncthreads();
    if (threadIdx.x == 0) {
        float tsum = 0.0f;
#pragma unroll
        for (int i = 0; i < WPB; i++) tsum += s[i];
        g_partials[blockIdx.x] = tsum;
        __threadfence();
        unsigned v = atomicAdd(&g_count, 1u);
        is_last = (v == GRID - 1);
    }
    __syncthreads();

    // Last block: deterministic final tree reduction over 512 partials.
    if (is_last) {
        __shared__ float r[BLOCK];
        r[threadIdx.x] = g_partials[threadIdx.x] + g_partials[threadIdx.x + BLOCK];
        __syncthreads();
#pragma unroll
        for (int off = BLOCK / 2; off > 0; off >>= 1) {
            if (threadIdx.x < off) r[threadIdx.x] += r[threadIdx.x + off];
            __syncthreads();
        }
        if (threadIdx.x == 0) {
            out[0] = r[0] * (1.0f / NELEM);
            g_count = 0;    // reset for graph replay
        }
    }
}

extern "C" void kernel_launch(void* const* d_in, const int* in_sizes, int n_in,
                              void* d_out, int out_size) {
    const float* labels = (const float*)d_in[0];
    float* out = (float*)d_out;
    opening_loss_kernel<<<GRID, BLOCK>>>(labels, out);
}